// round 1
// baseline (speedup 1.0000x reference)
#include <cuda_runtime.h>

// Problem constants
#define Bsz 2
#define Nn  4096
#define Cc  192
#define Hh  8
#define Dd  24
#define JCH 64          // j-rows per block in k_xw
#define NCHUNK 64       // chunks per batch in k_xw

// Scratch (no allocations allowed -> __device__ globals)
__device__ float g_wksum[Hh * Cc];                    // 1536
__device__ float g_ks[Bsz * Hh * Nn];                 // 64K
__device__ float g_w[Bsz * Hh * Nn];                  // 64K
__device__ float g_xwpart[Bsz * NCHUNK * Hh * Cc];    // 196K
__device__ __align__(16) float g_yrow[Bsz * Cc];      // 384

// ---------------------------------------------------------------------------
// K0: wk_sum[h,c] = sum_d W_qkv[(C + h*D + d), c]   (K-block rows of W_qkv)
// ---------------------------------------------------------------------------
__global__ void k_wksum(const float* __restrict__ Wqkv) {
    int idx = blockIdx.x * blockDim.x + threadIdx.x;
    if (idx >= Hh * Cc) return;
    int h = idx / Cc, c = idx % Cc;
    const float* base = Wqkv + (size_t)(Cc + h * Dd) * Cc + c;
    float s = 0.f;
#pragma unroll
    for (int d = 0; d < Dd; d++) s += base[(size_t)d * Cc];
    g_wksum[idx] = s;
}

// ---------------------------------------------------------------------------
// K1: ks[b,h,j] = x[b,j,:] . wk_sum[h,:]   — one warp per row, 8 warps/block
// ---------------------------------------------------------------------------
__global__ void k_ks(const float* __restrict__ x) {
    __shared__ float s_wks[Hh * Cc];
    for (int i = threadIdx.x; i < Hh * Cc; i += blockDim.x) s_wks[i] = g_wksum[i];
    __syncthreads();

    int warp = threadIdx.x >> 5;
    int lane = threadIdx.x & 31;
    int row  = blockIdx.x * 8 + warp;          // 0 .. B*N-1
    if (row >= Bsz * Nn) return;

    const float* xr = x + (size_t)row * Cc;
    float xv[6];
#pragma unroll
    for (int i = 0; i < 6; i++) xv[i] = xr[lane + 32 * i];

    int b = row >> 12;            // N = 4096
    int j = row & (Nn - 1);
    float r[Hh];
#pragma unroll
    for (int h = 0; h < Hh; h++) {
        float p = 0.f;
#pragma unroll
        for (int i = 0; i < 6; i++) p += xv[i] * s_wks[h * Cc + lane + 32 * i];
#pragma unroll
        for (int o = 16; o > 0; o >>= 1) p += __shfl_down_sync(0xffffffffu, p, o);
        r[h] = p;
    }
    if (lane == 0) {
#pragma unroll
        for (int h = 0; h < Hh; h++)
            g_ks[(size_t)(b * Hh + h) * Nn + j] = r[h];
    }
}

// ---------------------------------------------------------------------------
// K2: per-(b,h) softmax over N=4096 of (ks * scale) -> g_w
//     grid = 16 blocks, 256 threads, 16 values per thread kept in registers
// ---------------------------------------------------------------------------
__global__ void k_softmax(const float* __restrict__ scale) {
    const int bh  = blockIdx.x;
    const float s = scale[0];
    const float* ks = g_ks + (size_t)bh * Nn;
    float*       w  = g_w  + (size_t)bh * Nn;

    __shared__ float red[256];
    const int tid = threadIdx.x;

    float l[16];
    float m = -1e30f;
#pragma unroll
    for (int i = 0; i < 16; i++) {
        l[i] = ks[i * 256 + tid] * s;
        m = fmaxf(m, l[i]);
    }
    red[tid] = m; __syncthreads();
    for (int o = 128; o > 0; o >>= 1) {
        if (tid < o) red[tid] = fmaxf(red[tid], red[tid + o]);
        __syncthreads();
    }
    m = red[0]; __syncthreads();

    float z = 0.f;
#pragma unroll
    for (int i = 0; i < 16; i++) {
        l[i] = __expf(l[i] - m);
        z += l[i];
    }
    red[tid] = z; __syncthreads();
    for (int o = 128; o > 0; o >>= 1) {
        if (tid < o) red[tid] += red[tid + o];
        __syncthreads();
    }
    float invz = 1.f / red[0];
#pragma unroll
    for (int i = 0; i < 16; i++) w[i * 256 + tid] = l[i] * invz;
}

// ---------------------------------------------------------------------------
// K3: partial xw: block (b, chunk) handles JCH j-rows for ALL heads.
//     192 threads = one per channel c; x row read once, 8 FMA per element.
//     Writes per-block partials (deterministic reduce later, no atomics).
// ---------------------------------------------------------------------------
__global__ void k_xw(const float* __restrict__ x) {
    const int b     = blockIdx.x / NCHUNK;
    const int chunk = blockIdx.x % NCHUNK;
    const int j0    = chunk * JCH;

    __shared__ float w_s[Hh * JCH];
    for (int i = threadIdx.x; i < Hh * JCH; i += blockDim.x)
        w_s[i] = g_w[(size_t)(b * Hh + i / JCH) * Nn + j0 + (i % JCH)];
    __syncthreads();

    const int c = threadIdx.x;                 // 192 threads
    float acc[Hh];
#pragma unroll
    for (int h = 0; h < Hh; h++) acc[h] = 0.f;

    const float* xp = x + ((size_t)(b * Nn + j0)) * Cc + c;
#pragma unroll 4
    for (int jj = 0; jj < JCH; jj++) {
        float xv = xp[(size_t)jj * Cc];
#pragma unroll
        for (int h = 0; h < Hh; h++) acc[h] += w_s[h * JCH + jj] * xv;
    }
    float* out = g_xwpart + (size_t)blockIdx.x * (Hh * Cc);
#pragma unroll
    for (int h = 0; h < Hh; h++) out[h * Cc + c] = acc[h];
}

// ---------------------------------------------------------------------------
// K4: reduce partials -> xw[b,h,c]; outvec = xw @ W_v^T (per head);
//     yrow = outvec @ W_proj^T + b_proj.   grid = 2 blocks (one per batch).
// ---------------------------------------------------------------------------
__global__ void k_proj(const float* __restrict__ Wqkv,
                       const float* __restrict__ Wproj,
                       const float* __restrict__ bproj) {
    const int b = blockIdx.x;
    const int t = threadIdx.x;                 // 192 threads
    __shared__ float xw_s[Hh * Cc];
    __shared__ float ov_s[Cc];

    for (int e = t; e < Hh * Cc; e += Cc) {
        const float* p = g_xwpart + (size_t)(b * NCHUNK) * (Hh * Cc) + e;
        float s = 0.f;
#pragma unroll 8
        for (int blk = 0; blk < NCHUNK; blk++) s += p[(size_t)blk * (Hh * Cc)];
        xw_s[e] = s;
    }
    __syncthreads();

    // outvec[t]: t = h*D + d, V-block row of W_qkv is (2C + t)
    {
        const int h = t / Dd;
        const float* wv  = Wqkv + (size_t)(2 * Cc + t) * Cc;
        const float* xwh = xw_s + h * Cc;
        float s = 0.f;
#pragma unroll 8
        for (int c = 0; c < Cc; c++) s += xwh[c] * wv[c];
        ov_s[t] = s;
    }
    __syncthreads();

    float s = bproj[t];
    const float* wp = Wproj + (size_t)t * Cc;
#pragma unroll 8
    for (int c = 0; c < Cc; c++) s += ov_s[c] * wp[c];
    g_yrow[b * Cc + t] = s;
}

// ---------------------------------------------------------------------------
// K5: broadcast yrow[b,:] to all N rows of the output, float4-vectorized.
// ---------------------------------------------------------------------------
__global__ void k_bcast(float4* __restrict__ out) {
    __shared__ float4 yr[Bsz * 48];            // 192 floats per batch = 48 float4
    if (threadIdx.x < Bsz * 48)
        yr[threadIdx.x] = reinterpret_cast<const float4*>(g_yrow)[threadIdx.x];
    __syncthreads();

    const int total = Bsz * Nn * 48;           // 393216 float4
    for (int g = blockIdx.x * blockDim.x + threadIdx.x; g < total;
         g += gridDim.x * blockDim.x) {
        int r = g % 48;
        int b = (g >= Nn * 48) ? 1 : 0;
        out[g] = yr[b * 48 + r];
    }
}

// ---------------------------------------------------------------------------
extern "C" void kernel_launch(void* const* d_in, const int* in_sizes, int n_in,
                              void* d_out, int out_size) {
    const float* x     = (const float*)d_in[0];
    const float* Wqkv  = (const float*)d_in[1];
    const float* Wproj = (const float*)d_in[2];
    const float* bproj = (const float*)d_in[3];
    const float* scale = (const float*)d_in[4];

    k_wksum <<<6,    256>>>(Wqkv);
    k_ks    <<<1024, 256>>>(x);
    k_softmax<<<16,  256>>>(scale);
    k_xw    <<<Bsz * NCHUNK, Cc>>>(x);
    k_proj  <<<Bsz,  Cc>>>(Wqkv, Wproj, bproj);
    k_bcast <<<512,  256>>>((float4*)d_out);
}

// round 2
// speedup vs baseline: 2.2421x; 2.2421x over previous
#include <cuda_runtime.h>

#define Bsz 2
#define Nn  4096
#define Cc  192
#define Hh  8
#define Dd  24
#define NCHUNK 64           // chunks per batch (JCH = 64 j-rows each)
#define NBLK 148
#define NT   512

// Scratch (__device__ globals; no allocation allowed)
__device__ float g_wksum[Hh * Cc];
__device__ float g_ks[Bsz * Hh * Nn];
__device__ float g_w[Bsz * Hh * Nn];
__device__ float g_xwpart[Bsz * NCHUNK * Hh * Cc];
__device__ float g_ov[Bsz * Cc];
__device__ __align__(16) float g_yrow[Bsz * Cc];

// Grid barrier state (zero-init; count self-resets, gen is monotonic => replay-safe)
__device__ unsigned int g_bar_count = 0;
__device__ unsigned int g_bar_gen   = 0;

__device__ __forceinline__ void grid_sync() {
    __threadfence();                 // make this thread's global writes visible
    __syncthreads();
    if (threadIdx.x == 0) {
        volatile unsigned int* vgen = &g_bar_gen;
        unsigned int g0 = *vgen;     // read generation BEFORE arriving
        if (atomicAdd(&g_bar_count, 1u) == gridDim.x - 1u) {
            atomicExch(&g_bar_count, 0u);   // reset for next barrier
            __threadfence();                // reset visible before release
            atomicAdd(&g_bar_gen, 1u);      // release
        } else {
            while (*vgen == g0) __nanosleep(64);
        }
    }
    __syncthreads();
    __threadfence();                 // acquire side
}

__global__ __launch_bounds__(NT, 2)
void fused_kernel(const float* __restrict__ x,
                  const float* __restrict__ Wqkv,
                  const float* __restrict__ Wproj,
                  const float* __restrict__ bproj,
                  const float* __restrict__ scale,
                  float4* __restrict__ out) {
    __shared__ float sm[2048];
    const int tid  = threadIdx.x;
    const int bid  = blockIdx.x;
    const int warp = tid >> 5;
    const int lane = tid & 31;

    // ---------------- P0: wk_sum[h,c] = sum_d W_k[h*D+d, c] ----------------
    {
        int gid = bid * NT + tid;
        if (gid < Hh * Cc) {
            int h = gid / Cc, c = gid % Cc;
            const float* base = Wqkv + (size_t)(Cc + h * Dd) * Cc + c;
            float s = 0.f;
#pragma unroll
            for (int d = 0; d < Dd; d++) s += base[(size_t)d * Cc];
            g_wksum[gid] = s;
        }
    }
    grid_sync();

    // ---------------- P1: ks[b,h,j] = x[row,:] . wk_sum[h,:] ----------------
    {
        for (int i = tid; i < Hh * Cc; i += NT) sm[i] = g_wksum[i];
        __syncthreads();
        const int nwarps = NBLK * (NT / 32);   // 2368
        for (int row = bid * (NT / 32) + warp; row < Bsz * Nn; row += nwarps) {
            const float* xr = x + (size_t)row * Cc;
            float xv[6];
#pragma unroll
            for (int i = 0; i < 6; i++) xv[i] = xr[lane + 32 * i];
            int b = row >> 12, j = row & (Nn - 1);
#pragma unroll
            for (int h = 0; h < Hh; h++) {
                float p = 0.f;
#pragma unroll
                for (int i = 0; i < 6; i++) p += xv[i] * sm[h * Cc + lane + 32 * i];
#pragma unroll
                for (int o = 16; o > 0; o >>= 1) p += __shfl_down_sync(0xffffffffu, p, o);
                if (lane == 0) g_ks[(size_t)(b * Hh + h) * Nn + j] = p;
            }
        }
    }
    grid_sync();

    // ---------------- P2: softmax per (b,h) — blocks 0..15 ----------------
    if (bid < Bsz * Hh) {
        const float s = scale[0];
        const float* ks = g_ks + (size_t)bid * Nn;
        float*       w  = g_w  + (size_t)bid * Nn;
        float l[8];
        float m = -1e30f;
#pragma unroll
        for (int i = 0; i < 8; i++) { l[i] = ks[i * NT + tid] * s; m = fmaxf(m, l[i]); }
        sm[tid] = m; __syncthreads();
        for (int o = NT / 2; o > 0; o >>= 1) {
            if (tid < o) sm[tid] = fmaxf(sm[tid], sm[tid + o]);
            __syncthreads();
        }
        m = sm[0]; __syncthreads();
        float z = 0.f;
#pragma unroll
        for (int i = 0; i < 8; i++) { l[i] = __expf(l[i] - m); z += l[i]; }
        sm[tid] = z; __syncthreads();
        for (int o = NT / 2; o > 0; o >>= 1) {
            if (tid < o) sm[tid] += sm[tid + o];
            __syncthreads();
        }
        float inv = 1.f / sm[0];
#pragma unroll
        for (int i = 0; i < 8; i++) w[i * NT + tid] = l[i] * inv;
    }
    grid_sync();

    // ---------------- P3: partial xw — blocks 0..127, 2-way j split ----------------
    if (bid < Bsz * NCHUNK) {
        const int b  = bid >> 6;
        const int j0 = (bid & 63) * 64;
        for (int i = tid; i < Hh * 64; i += NT)
            sm[i] = g_w[(size_t)(b * Hh + (i >> 6)) * Nn + j0 + (i & 63)];
        __syncthreads();

        const int jg = tid / Cc;          // 0 or 1 (tid<384)
        const int c  = tid % Cc;
        float acc[Hh];
#pragma unroll
        for (int h = 0; h < Hh; h++) acc[h] = 0.f;
        if (tid < 2 * Cc) {
            const float* xp = x + ((size_t)(b * Nn + j0 + jg * 32)) * Cc + c;
#pragma unroll 4
            for (int jj = 0; jj < 32; jj++) {
                float xv = xp[(size_t)jj * Cc];
                int wj = jg * 32 + jj;
#pragma unroll
                for (int h = 0; h < Hh; h++) acc[h] += sm[h * 64 + wj] * xv;
            }
        }
        __syncthreads();
        if (tid >= Cc && tid < 2 * Cc) {
#pragma unroll
            for (int h = 0; h < Hh; h++) sm[512 + h * Cc + c] = acc[h];
        }
        __syncthreads();
        if (tid < Cc) {
            float* po = g_xwpart + (size_t)bid * (Hh * Cc);
#pragma unroll
            for (int h = 0; h < Hh; h++)
                po[h * Cc + c] = acc[h] + sm[512 + h * Cc + c];
        }
    }
    grid_sync();

    // ---------------- P4a: reduce partials + per-head V projection — blocks 0..15 ----------------
    if (bid < Bsz * Hh) {
        const int b = bid >> 3, h = bid & 7;
        const int kg = tid / Cc;          // 0 or 1 (tid<384)
        const int c  = tid % Cc;
        float s1 = 0.f;
        if (tid < 2 * Cc) {
            const float* p = g_xwpart + ((size_t)(b * NCHUNK + kg * 32)) * (Hh * Cc) + h * Cc + c;
#pragma unroll 8
            for (int k = 0; k < 32; k++) s1 += p[(size_t)k * (Hh * Cc)];
        }
        __syncthreads();
        if (tid >= Cc && tid < 2 * Cc) sm[c] = s1;
        __syncthreads();
        if (tid < Cc) sm[256 + c] = s1 + sm[c];   // xw[b,h,c]
        __syncthreads();

        // ov[b, h*D+d] = xw[b,h,:] . W_v[2C + h*D + d, :]   (24 dots, warp each)
        for (int d = warp; d < Dd; d += NT / 32) {
            const float* wv = Wqkv + (size_t)(2 * Cc + h * Dd + d) * Cc;
            float p = 0.f;
#pragma unroll
            for (int i = 0; i < 6; i++) p += sm[256 + lane + 32 * i] * wv[lane + 32 * i];
#pragma unroll
            for (int o = 16; o > 0; o >>= 1) p += __shfl_down_sync(0xffffffffu, p, o);
            if (lane == 0) g_ov[b * Cc + h * Dd + d] = p;
        }
    }
    grid_sync();

    // ---------------- P4b: final projection row — blocks 0,1 ----------------
    if (bid < Bsz) {
        for (int i = tid; i < Cc; i += NT) sm[i] = g_ov[bid * Cc + i];
        __syncthreads();
        if (tid < Cc) {
            const float4* wp = (const float4*)(Wproj + (size_t)tid * Cc);
            float s = bproj[tid];
#pragma unroll
            for (int q = 0; q < 48; q++) {
                float4 v = wp[q];
                s += v.x * sm[4 * q] + v.y * sm[4 * q + 1]
                   + v.z * sm[4 * q + 2] + v.w * sm[4 * q + 3];
            }
            g_yrow[bid * Cc + tid] = s;
        }
    }
    grid_sync();

    // ---------------- P5: broadcast y rows to output ----------------
    {
        if (tid < Bsz * 48)
            ((float4*)sm)[tid] = ((const float4*)g_yrow)[tid];
        __syncthreads();
        const int total = Bsz * Nn * 48;           // 393216 float4
        for (int g = bid * NT + tid; g < total; g += NBLK * NT) {
            int r   = g % 48;
            int row = g / 48;
            int b   = row >> 12;
            out[g] = ((float4*)sm)[b * 48 + r];
        }
    }
}

extern "C" void kernel_launch(void* const* d_in, const int* in_sizes, int n_in,
                              void* d_out, int out_size) {
    const float* x     = (const float*)d_in[0];
    const float* Wqkv  = (const float*)d_in[1];
    const float* Wproj = (const float*)d_in[2];
    const float* bproj = (const float*)d_in[3];
    const float* scale = (const float*)d_in[4];

    fused_kernel<<<NBLK, NT>>>(x, Wqkv, Wproj, bproj, scale, (float4*)d_out);
}

// round 3
// speedup vs baseline: 2.3753x; 1.0594x over previous
#include <cuda_runtime.h>

#define Bsz 2
#define Nn  4096
#define Cc  192
#define Hh  8
#define Dd  24
#define JCH 64                 // j-rows per xw chunk
#define NCH 64                 // chunks per batch
#define NTASK (Bsz * NCH)      // 128 xw tasks
#define NBLK 296
#define NT   512

// Scratch (__device__ globals; no allocation allowed)
__device__ float g_e[Bsz * Hh * Nn];                        // exp(ks*s), unnormalized
__device__ __align__(16) float g_xwpart[NTASK * Hh * Cc];   // per-chunk partial xw'
__device__ float g_zpart[Bsz * Hh * NCH];                   // per-chunk partial Z
__device__ __align__(16) float g_yrow[Bsz * Cc];

// Grid barrier (zero-init; count self-resets, gen monotonic => graph-replay safe)
__device__ unsigned int g_bar_count = 0;
__device__ unsigned int g_bar_gen   = 0;

__device__ __forceinline__ void grid_sync() {
    __threadfence();
    __syncthreads();
    if (threadIdx.x == 0) {
        volatile unsigned int* vgen = &g_bar_gen;
        unsigned int g0 = *vgen;                      // read gen BEFORE arriving
        if (atomicAdd(&g_bar_count, 1u) == (unsigned)(NBLK - 1)) {
            atomicExch(&g_bar_count, 0u);
            __threadfence();
            atomicAdd(&g_bar_gen, 1u);                // release
        } else {
            while (*vgen == g0) __nanosleep(32);
        }
    }
    __syncthreads();
    __threadfence();
}

__global__ __launch_bounds__(NT, 2)
void fused_kernel(const float* __restrict__ x,
                  const float* __restrict__ Wqkv,
                  const float* __restrict__ Wproj,
                  const float* __restrict__ bproj,
                  const float* __restrict__ scale,
                  float4* __restrict__ out) {
    __shared__ float sm[2048];
    const int tid  = threadIdx.x;
    const int bid  = blockIdx.x;
    const int warp = tid >> 5;
    const int lane = tid & 31;

    // =============== Phase A: wksum (redundant, smem) + e = exp(ks*s) ===============
    {
        // wk_sum[h,c] = sum_d W_k[(C + h*D + d), c]  -> sm[h*192+c]
        for (int e = tid; e < Hh * Cc; e += NT) {
            int h = e / Cc, c = e - h * Cc;
            const float* base = Wqkv + (size_t)(Cc + h * Dd) * Cc + c;
            float s = 0.f;
#pragma unroll
            for (int d = 0; d < Dd; d++) s += base[(size_t)d * Cc];
            sm[e] = s;
        }
        __syncthreads();
        const float s = __ldg(scale);
        const int nwarps = NBLK * (NT / 32);          // 4736
        for (int row = bid * (NT / 32) + warp; row < Bsz * Nn; row += nwarps) {
            const float* xr = x + (size_t)row * Cc;
            float xv[6];
#pragma unroll
            for (int i = 0; i < 6; i++) xv[i] = xr[lane + 32 * i];
            int b = row >> 12, j = row & (Nn - 1);
#pragma unroll
            for (int h = 0; h < Hh; h++) {
                float p = 0.f;
#pragma unroll
                for (int i = 0; i < 6; i++) p += xv[i] * sm[h * Cc + lane + 32 * i];
#pragma unroll
                for (int o = 16; o > 0; o >>= 1) p += __shfl_down_sync(0xffffffffu, p, o);
                if (lane == 0)
                    g_e[(size_t)(b * Hh + h) * Nn + j] = __expf(p * s);
            }
        }
    }
    grid_sync();

    // =============== Phase C: per-chunk partial xw' and Z (128 tasks) ===============
    if (bid < NTASK) {
        const int b  = bid >> 6;
        const int j0 = (bid & 63) * JCH;
        // stage e values: sm[h*64 + jj], 512 floats
        sm[tid] = g_e[(size_t)(b * Hh + (tid >> 6)) * Nn + j0 + (tid & 63)];
        __syncthreads();

        const int jg = tid / Cc;              // 0,1 compute; 2 = Z warps
        const int c  = tid - jg * Cc;
        float acc[Hh];
#pragma unroll
        for (int h = 0; h < Hh; h++) acc[h] = 0.f;

        if (jg < 2) {
            const float* xp = x + ((size_t)(b * Nn + j0 + jg * 32)) * Cc + c;
#pragma unroll 4
            for (int jj = 0; jj < 32; jj++) {
                float xv = xp[(size_t)jj * Cc];
                int wj = jg * 32 + jj;
#pragma unroll
                for (int h = 0; h < Hh; h++) acc[h] += sm[h * 64 + wj] * xv;
            }
        } else if (warp >= 12) {              // tids 384..511: Z partials, 4 warps x 2 heads
            int h = (warp - 12) * 2 + (lane >> 4);
            int l = lane & 15;
            float z = sm[h * 64 + l] + sm[h * 64 + 16 + l]
                    + sm[h * 64 + 32 + l] + sm[h * 64 + 48 + l];
#pragma unroll
            for (int o = 8; o > 0; o >>= 1) z += __shfl_xor_sync(0xffffffffu, z, o);
            if (l == 0) g_zpart[(b * Hh + h) * NCH + (bid & 63)] = z;
        }
        __syncthreads();
        if (jg == 1) {
#pragma unroll
            for (int h = 0; h < Hh; h++) sm[512 + h * Cc + c] = acc[h];
        }
        __syncthreads();
        if (jg == 0) {
            float* po = g_xwpart + (size_t)bid * (Hh * Cc);
#pragma unroll
            for (int h = 0; h < Hh; h++)
                po[h * Cc + c] = acc[h] + sm[512 + h * Cc + c];
        }
    }
    grid_sync();

    // =============== Phase D: tail per batch (2 blocks): reduce -> invZ -> Vproj -> yrow ===============
    if (bid < Bsz) {
        const int b = bid;
        // reduce 64 chunk partials, float4: 384 f4-columns
        if (tid < 384) {
            const float4* p = (const float4*)(g_xwpart + (size_t)(b * NCH) * (Hh * Cc)) + tid;
            float4 s = make_float4(0.f, 0.f, 0.f, 0.f);
#pragma unroll 8
            for (int k = 0; k < NCH; k++) {
                float4 v = p[(size_t)k * 384];
                s.x += v.x; s.y += v.y; s.z += v.z; s.w += v.w;
            }
            ((float4*)sm)[tid] = s;           // sm[0..1535] = xw'[h*192+c]
        }
        // invZ per head: warps 0..7 (they also did the f4 loop; sequential is fine)
        __syncthreads();
        if (warp < Hh) {
            const float* zp = g_zpart + (b * Hh + warp) * NCH;
            float z = zp[lane] + zp[lane + 32];
#pragma unroll
            for (int o = 16; o > 0; o >>= 1) z += __shfl_xor_sync(0xffffffffu, z, o);
            if (lane == 0) sm[1536 + warp] = 1.f / z;
        }
        __syncthreads();
        // ov[t] = invZ[h] * xw'[h,:] . W_v[2C+t,:]
        if (tid < Cc) {
            int h = tid / Dd;
            const float4* wv = (const float4*)(Wqkv + (size_t)(2 * Cc + tid) * Cc);
            const float4* xw = (const float4*)(sm + h * Cc);
            float s = 0.f;
#pragma unroll
            for (int q = 0; q < 48; q++) {
                float4 wvv = wv[q], xwv = xw[q];
                s += wvv.x * xwv.x + wvv.y * xwv.y + wvv.z * xwv.z + wvv.w * xwv.w;
            }
            sm[1544 + tid] = s * sm[1536 + h];
        }
        __syncthreads();
        // yrow[t] = bproj[t] + ov . Wproj[t,:]
        if (tid < Cc) {
            const float4* wp = (const float4*)(Wproj + (size_t)tid * Cc);
            const float4* ov = (const float4*)(sm + 1544);
            float s = bproj[tid];
#pragma unroll
            for (int q = 0; q < 48; q++) {
                float4 wpv = wp[q], ovv = ov[q];
                s += wpv.x * ovv.x + wpv.y * ovv.y + wpv.z * ovv.z + wpv.w * ovv.w;
            }
            g_yrow[b * Cc + tid] = s;
        }
    }
    grid_sync();

    // =============== Phase E: broadcast y rows to output ===============
    {
        if (tid < Bsz * 48)
            ((float4*)sm)[tid] = ((const float4*)g_yrow)[tid];
        __syncthreads();
        const int total = Bsz * Nn * 48;              // 393216 float4
        for (int g = bid * NT + tid; g < total; g += NBLK * NT) {
            int r = g % 48;
            int b = (g >= Nn * 48) ? 1 : 0;
            out[g] = ((float4*)sm)[b * 48 + r];
        }
    }
}

extern "C" void kernel_launch(void* const* d_in, const int* in_sizes, int n_in,
                              void* d_out, int out_size) {
    const float* x     = (const float*)d_in[0];
    const float* Wqkv  = (const float*)d_in[1];
    const float* Wproj = (const float*)d_in[2];
    const float* bproj = (const float*)d_in[3];
    const float* scale = (const float*)d_in[4];

    fused_kernel<<<NBLK, NT>>>(x, Wqkv, Wproj, bproj, scale, (float4*)d_out);
}

// round 4
// speedup vs baseline: 3.6300x; 1.5282x over previous
#include <cuda_runtime.h>

#define Bsz 2
#define Nn  4096
#define Cc  192
#define Hh  8
#define Dd  24
#define JCH 32                  // j-rows per task
#define NCH 128                 // chunks per batch
#define NTASK (Bsz * NCH)       // 256
#define NBLK 256
#define NT   512

#define FPSCALE 4194304.0f      // 2^22
#define FPINV   (1.0f / 4194304.0f)

// Scratch (__device__ globals; no allocations allowed)
__device__ float g_wksum[Hh * Cc];
__device__ __align__(16) float g_xwpart[NTASK * Hh * Cc];
__device__ float g_zpart[Bsz * Hh * NCH];
__device__ unsigned long long g_yfp[Bsz * Cc];   // fixed-point yrow accumulator

// Grid barrier (zero-init; count self-resets, gen monotonic => graph-replay safe)
__device__ unsigned int g_bar_count = 0;
__device__ unsigned int g_bar_gen   = 0;

__device__ __forceinline__ void grid_sync() {
    __threadfence();
    __syncthreads();
    if (threadIdx.x == 0) {
        volatile unsigned int* vgen = &g_bar_gen;
        unsigned int g0 = *vgen;
        if (atomicAdd(&g_bar_count, 1u) == (unsigned)(NBLK - 1)) {
            atomicExch(&g_bar_count, 0u);
            __threadfence();
            atomicAdd(&g_bar_gen, 1u);
        } else {
            while (*vgen == g0) __nanosleep(32);
        }
    }
    __syncthreads();
    __threadfence();
}

// ---------------------------------------------------------------------------
// Prelude: wk_sum[h,c] = sum_d W_k[(C+h*D+d), c]; zero the y accumulator.
// grid = 3 x 512 (exactly 1536 threads)
// ---------------------------------------------------------------------------
__global__ void k_pre(const float* __restrict__ Wqkv) {
    int gid = blockIdx.x * 512 + threadIdx.x;      // 0..1535
    if (gid < Bsz * Cc) g_yfp[gid] = 0ull;
    int h = gid / Cc, c = gid - h * Cc;
    const float* base = Wqkv + (size_t)(Cc + h * Dd) * Cc + c;
    float s = 0.f;
#pragma unroll
    for (int d = 0; d < Dd; d++) s += base[(size_t)d * Cc];
    g_wksum[gid] = s;
}

// ---------------------------------------------------------------------------
__global__ __launch_bounds__(NT, 2)
void fused_kernel(const float* __restrict__ x,
                  const float* __restrict__ Wqkv,
                  const float* __restrict__ Wproj,
                  const float* __restrict__ bproj,
                  const float* __restrict__ scale,
                  float4* __restrict__ out) {
    __shared__ float s_ws[Hh * Cc];                       // 1536
    __shared__ float s_e[Hh * JCH];                       // 256
    __shared__ __align__(16) float s_comb[Hh * Cc];       // 1536 (also D staging)
    __shared__ __align__(16) float s_xw[Cc];              // 192
    __shared__ float s_ov[Dd];
    __shared__ float s_invz;
    __shared__ __align__(16) float s_y[Bsz * Cc];         // 384

    const int tid  = threadIdx.x;
    const int bid  = blockIdx.x;
    const int warp = tid >> 5;
    const int lane = tid & 31;

    // =============== Phase AC: e (local) -> xw partial + Z partial ===============
    {
        const int b     = bid >> 7;                // 128 chunks per batch
        const int chunk = bid & 127;
        const int j0    = chunk * JCH;

        for (int i = tid; i < Hh * Cc; i += NT) s_ws[i] = g_wksum[i];
        __syncthreads();

        const float sc = __ldg(scale);
        // e for 32 rows: 16 warps x 2 rows
#pragma unroll
        for (int r = 0; r < 2; r++) {
            const int jj = warp * 2 + r;
            const float* xr = x + (size_t)(b * Nn + j0 + jj) * Cc;
            float xv[6];
#pragma unroll
            for (int i = 0; i < 6; i++) xv[i] = xr[lane + 32 * i];
#pragma unroll
            for (int h = 0; h < Hh; h++) {
                float p = 0.f;
#pragma unroll
                for (int i = 0; i < 6; i++) p += xv[i] * s_ws[h * Cc + lane + 32 * i];
#pragma unroll
                for (int o = 16; o > 0; o >>= 1) p += __shfl_down_sync(0xffffffffu, p, o);
                if (lane == 0) s_e[h * JCH + jj] = __expf(p * sc);
            }
        }
        __syncthreads();

        // xw partial: threads 0..383 = (jg, c); Z partial: warps 12..15
        const int jg = tid / Cc;
        const int c  = tid - jg * Cc;
        float acc[Hh];
#pragma unroll
        for (int h = 0; h < Hh; h++) acc[h] = 0.f;

        if (tid < 2 * Cc) {
            const float* xp = x + ((size_t)(b * Nn + j0 + jg * 16)) * Cc + c;
#pragma unroll 8
            for (int q = 0; q < 16; q++) {
                float xv = xp[(size_t)q * Cc];
                int wj = jg * 16 + q;
#pragma unroll
                for (int h = 0; h < Hh; h++) acc[h] += s_e[h * JCH + wj] * xv;
            }
        } else if (warp >= 12) {                   // tids 384..511
            int h = (warp - 12) * 2 + (lane >> 4);
            int l = lane & 15;
            float z = s_e[h * JCH + l] + s_e[h * JCH + 16 + l];
#pragma unroll
            for (int o = 8; o > 0; o >>= 1) z += __shfl_xor_sync(0xffffffffu, z, o);
            if (l == 0) g_zpart[(b * Hh + h) * NCH + chunk] = z;
        }
        __syncthreads();
        if (jg == 1) {
#pragma unroll
            for (int h = 0; h < Hh; h++) s_comb[h * Cc + c] = acc[h];
        }
        __syncthreads();
        if (jg == 0) {
#pragma unroll
            for (int h = 0; h < Hh; h++) s_comb[h * Cc + c] += acc[h];
        }
        __syncthreads();
        if (tid < 384)
            ((float4*)g_xwpart)[bid * 384 + tid] = ((const float4*)s_comb)[tid];
    }
    grid_sync();

    // =============== Phase D: 16 blocks (b,h): reduce + Vproj + yrow atomics ===============
    if (bid < Bsz * Hh) {
        const int b = bid >> 3, h = bid & 7;

        if (tid < 384) {                           // (slice 0..7) x (col 0..47)
            const int col = tid % 48, slice = tid / 48;
            const float4* p = (const float4*)g_xwpart;
            int base = (b * NCH + slice * 16) * 384 + h * 48 + col;
            float4 s = make_float4(0.f, 0.f, 0.f, 0.f);
#pragma unroll
            for (int k = 0; k < 16; k++) {
                float4 v = p[base + k * 384];
                s.x += v.x; s.y += v.y; s.z += v.z; s.w += v.w;
            }
            ((float4*)s_comb)[tid] = s;
        }
        if (warp == 15) {                          // Z reduce (128 partials)
            const float* zp = g_zpart + (b * Hh + h) * NCH;
            float z = zp[lane] + zp[lane + 32] + zp[lane + 64] + zp[lane + 96];
#pragma unroll
            for (int o = 16; o > 0; o >>= 1) z += __shfl_xor_sync(0xffffffffu, z, o);
            if (lane == 0) s_invz = 1.f / z;
        }
        __syncthreads();
        if (tid < 48) {
            float4 a = make_float4(0.f, 0.f, 0.f, 0.f);
#pragma unroll
            for (int sl = 0; sl < 8; sl++) {
                float4 v = ((const float4*)s_comb)[sl * 48 + tid];
                a.x += v.x; a.y += v.y; a.z += v.z; a.w += v.w;
            }
            ((float4*)s_xw)[tid] = a;
        }
        __syncthreads();

        // V projection: warps 0..11, 2 d's each; apply invZ here
        if (warp < 12) {
#pragma unroll
            for (int dd = 0; dd < 2; dd++) {
                int d = warp * 2 + dd;
                const float* wv = Wqkv + (size_t)(2 * Cc + h * Dd + d) * Cc;
                float p = 0.f;
#pragma unroll
                for (int i = 0; i < 6; i++) p += s_xw[lane + 32 * i] * wv[lane + 32 * i];
#pragma unroll
                for (int o = 16; o > 0; o >>= 1) p += __shfl_down_sync(0xffffffffu, p, o);
                if (lane == 0) s_ov[d] = p * s_invz;
            }
        }
        __syncthreads();

        // yrow partial for this head (int64 fixed point => deterministic)
        if (tid < Cc) {
            const float* wp = Wproj + (size_t)tid * Cc + h * Dd;
            float s = 0.f;
#pragma unroll
            for (int d = 0; d < Dd; d++) s += s_ov[d] * wp[d];
            atomicAdd(&g_yfp[b * Cc + tid],
                      (unsigned long long)__float2ll_rn(s * FPSCALE));
        }
    }
    grid_sync();

    // =============== Phase E: convert + broadcast ===============
    {
        if (tid < Bsz * Cc) {
            long long v = (long long)g_yfp[tid];
            s_y[tid] = (float)v * FPINV + bproj[tid % Cc];
        }
        __syncthreads();
        const float4* sy4 = (const float4*)s_y;
        const int base = bid * 1536;               // 256 * 1536 = 393216 float4
#pragma unroll
        for (int k = 0; k < 3; k++) {
            int g   = base + k * NT + tid;
            int r   = g % 48;
            int row = g / 48;
            int b   = row >> 12;
            out[g] = sy4[b * 48 + r];
        }
    }
}

extern "C" void kernel_launch(void* const* d_in, const int* in_sizes, int n_in,
                              void* d_out, int out_size) {
    const float* x     = (const float*)d_in[0];
    const float* Wqkv  = (const float*)d_in[1];
    const float* Wproj = (const float*)d_in[2];
    const float* bproj = (const float*)d_in[3];
    const float* scale = (const float*)d_in[4];

    k_pre<<<3, 512>>>(Wqkv);
    fused_kernel<<<NBLK, NT>>>(x, Wqkv, Wproj, bproj, scale, (float4*)d_out);
}